// round 8
// baseline (speedup 1.0000x reference)
#include <cuda_runtime.h>
#include <cuda_fp16.h>
#include <cstdint>

// Problem constants: F=50000, K=32, E=128, N_NODE=100000
#define KNBR 32
#define EMB  128
#define MAXF 50000
#define MAXN 100000

// Scratch (no cudaMalloc allowed)
__device__ float g_p[MAXN];                                // 0.4 MB
__device__ alignas(16) __half g_emb_h [MAXN * EMB];        // 25.6 MB
__device__ alignas(16) __half g_embf_h[MAXF * EMB];        // 12.8 MB
__device__ unsigned g_tile_ctr;

// ---------------------------------------------------------------------------
// PTX helpers
// ---------------------------------------------------------------------------
__device__ __forceinline__ void ldsm_x4(uint32_t& r0, uint32_t& r1,
                                        uint32_t& r2, uint32_t& r3, uint32_t a)
{
    asm volatile("ldmatrix.sync.aligned.m8n8.x4.shared.b16 {%0,%1,%2,%3}, [%4];"
                 : "=r"(r0), "=r"(r1), "=r"(r2), "=r"(r3) : "r"(a));
}
__device__ __forceinline__ void ldsm_x4_t(uint32_t& r0, uint32_t& r1,
                                          uint32_t& r2, uint32_t& r3, uint32_t a)
{
    asm volatile("ldmatrix.sync.aligned.m8n8.x4.trans.shared.b16 {%0,%1,%2,%3}, [%4];"
                 : "=r"(r0), "=r"(r1), "=r"(r2), "=r"(r3) : "r"(a));
}
__device__ __forceinline__ void mma16816(float* d, const uint32_t* a,
                                         uint32_t b0, uint32_t b1)
{
    asm volatile(
        "mma.sync.aligned.m16n8k16.row.col.f32.f16.f16.f32 "
        "{%0,%1,%2,%3}, {%4,%5,%6,%7}, {%8,%9}, {%0,%1,%2,%3};"
        : "+f"(d[0]), "+f"(d[1]), "+f"(d[2]), "+f"(d[3])
        : "r"(a[0]), "r"(a[1]), "r"(a[2]), "r"(a[3]), "r"(b0), "r"(b1));
}
__device__ __forceinline__ void cp_async16(uint32_t saddr, const void* gaddr)
{
    asm volatile("cp.async.cg.shared.global [%0], [%1], 16;"
                 :: "r"(saddr), "l"(gaddr));
}

// ---------------------------------------------------------------------------
// Kernel RESET: zero the tile work-queue counter (every launch/replay).
// ---------------------------------------------------------------------------
__global__ void reset_kernel() { g_tile_ctr = 0u; }

// ---------------------------------------------------------------------------
// Kernel PRE: blocks [0, nblk_p): p[n] = dot(emb_i[n], u) + fp16 copy of emb_i
//             blocks [nblk_p, ..): fp16 copy of emb_f
// ---------------------------------------------------------------------------
__global__ __launch_bounds__(256) void pre_kernel(
    const float* __restrict__ emb_i, const float* __restrict__ emb_f,
    const float* __restrict__ u, int N, int F, int nblk_p)
{
    if (blockIdx.x < (unsigned)nblk_p) {
        int gw   = (blockIdx.x * 256 + threadIdx.x) >> 5;
        int lane = threadIdx.x & 31;
        if (gw >= N) return;
        float4 v  = *reinterpret_cast<const float4*>(emb_i + (size_t)gw * EMB + lane * 4);
        float4 uu = *reinterpret_cast<const float4*>(u + lane * 4);

        __half2 h0 = __float22half2_rn(make_float2(v.x, v.y));
        __half2 h1 = __float22half2_rn(make_float2(v.z, v.w));
        uint2 hw;
        hw.x = *reinterpret_cast<uint32_t*>(&h0);
        hw.y = *reinterpret_cast<uint32_t*>(&h1);
        *reinterpret_cast<uint2*>(&g_emb_h[(size_t)gw * EMB + lane * 4]) = hw;

        float s = v.x * uu.x + v.y * uu.y + v.z * uu.z + v.w * uu.w;
#pragma unroll
        for (int off = 16; off > 0; off >>= 1)
            s += __shfl_xor_sync(0xffffffffu, s, off);
        if (lane == 0) g_p[gw] = s;
    } else {
        int id = (blockIdx.x - nblk_p) * 256 + threadIdx.x;   // float4 index
        size_t base = (size_t)id * 4;
        if (base >= (size_t)F * EMB) return;
        float4 v = *reinterpret_cast<const float4*>(emb_f + base);
        __half2 h0 = __float22half2_rn(make_float2(v.x, v.y));
        __half2 h1 = __float22half2_rn(make_float2(v.z, v.w));
        uint2 hw;
        hw.x = *reinterpret_cast<uint32_t*>(&h0);
        hw.y = *reinterpret_cast<uint32_t*>(&h1);
        *reinterpret_cast<uint2*>(&g_embf_h[base]) = hw;
    }
}

// ---------------------------------------------------------------------------
// FUSED kernel: per 64-f tile:
//  phase 1: warp-per-feature softmax + fp16 gather-aggregate -> s_cat[:,128:256]
//           (cp.async streams emb_f fp16 -> s_cat[:,0:128] under the gather)
//  phase 2: HMMA mainloop (m16n8k16, fp32 acc), K=256
//  phase 3: epilogue: gate=sigmoid(x+b); out = g*ef + (1-g)*agg, ef/agg fp16
//           read back from s_cat (no global reads except bias).
// Persistent, 2 CTAs/SM, atomic tile queue. 256 thr = 8 warps (4f x 2e MMA).
// ---------------------------------------------------------------------------
#define TM 64
#define W_LDH   136                      // halves per k-row (128 + 8 pad)
#define CAT_LDH 264                      // halves per f-row (256 + 8 pad)
#define S_W_HALFS    (256 * W_LDH)       // 69632 B
#define S_CAT_HALFS  (TM * CAT_LDH)      // 33792 B
#define SMEM_FUSED_B ((S_W_HALFS + S_CAT_HALFS) * 2)     // 103424 B

__global__ __launch_bounds__(256, 2) void fused_kernel(
    const int* __restrict__ adj,      // [F, 32]
    const float* __restrict__ W,      // [128, 256]
    const float* __restrict__ bias,   // [128]
    float* __restrict__ out,          // [F, 128]
    int F)
{
    extern __shared__ __half hsmem[];
    __half* s_w   = hsmem;                 // [k=0..255][n=0..127] (+pad)
    __half* s_cat = hsmem + S_W_HALFS;     // [f=0..63][k=0..255] (+pad)
    __shared__ int s_tile;

    const int t    = threadIdx.x;
    const int lane = t & 31;
    const int wid  = t >> 5;
    const int f0   = (wid >> 1) * 16;      // MMA warp f-offset
    const int nb   = (wid & 1) * 64;       // MMA warp n-offset
    const int ntiles = (F + TM - 1) / TM;

    // ---- W -> fp16 smem [k][n] transposed, once per block ----
#pragma unroll
    for (int r = 0; r < 32; r++) {
        int id = t + 256 * r;             // 8192 float4 = 128e x 64jq
        int e  = id >> 6;
        int jq = id & 63;
        float4 v = *reinterpret_cast<const float4*>(W + e * 256 + jq * 4);
        s_w[(jq * 4 + 0) * W_LDH + e] = __float2half_rn(v.x);
        s_w[(jq * 4 + 1) * W_LDH + e] = __float2half_rn(v.y);
        s_w[(jq * 4 + 2) * W_LDH + e] = __float2half_rn(v.z);
        s_w[(jq * 4 + 3) * W_LDH + e] = __float2half_rn(v.w);
    }

    const uint32_t s_cat_u = (uint32_t)__cvta_generic_to_shared(s_cat);
    const uint32_t s_w_u   = (uint32_t)__cvta_generic_to_shared(s_w);

    const uint32_t a_lane_addr = s_cat_u +
        (uint32_t)(((f0 + (lane & 15)) * CAT_LDH + (lane >> 4) * 8) * 2);
    const uint32_t b_lane_addr = s_w_u +
        (uint32_t)(((((lane >> 3) & 1) * 8 + (lane & 7)) * W_LDH
                    + nb + (lane >> 4) * 8) * 2);

    const uint2* ebase = reinterpret_cast<const uint2*>(g_emb_h);

    for (;;) {
        __syncthreads();     // prior epilogue done with s_cat (and W load, iter 0)
        if (t == 0) s_tile = (int)atomicAdd(&g_tile_ctr, 1u);
        __syncthreads();
        const int tile = s_tile;
        if (tile >= ntiles) break;
        const int fbase = tile * TM;

        // ---- cp.async: emb_f fp16 -> s_cat[:, 0:128]; flies under gather ----
#pragma unroll
        for (int r = 0; r < 4; r++) {
            int id  = t + 256 * r;           // 1024 chunks of 16B
            int row = id >> 4;               // 0..63
            int c   = id & 15;               // chunk 0..15
            int gf  = fbase + row; if (gf >= F) gf = F - 1;
            cp_async16(s_cat_u + (uint32_t)((row * CAT_LDH + c * 8) * 2),
                       g_embf_h + (size_t)gf * EMB + c * 8);
        }
        asm volatile("cp.async.commit_group;");

        // ---- Phase 1: softmax + gather-aggregate (warp per feature) ----
#pragma unroll 1
        for (int rr = 0; rr < 8; rr++) {
            const int row = wid * 8 + rr;
            int gf = fbase + row; if (gf >= F) gf = F - 1;

            int   idx = adj[(size_t)gf * KNBR + lane];
            float a = g_p[idx] + (idx != 0 ? 0.0f : -10000.0f);
            float m = a;
#pragma unroll
            for (int off = 16; off > 0; off >>= 1)
                m = fmaxf(m, __shfl_xor_sync(0xffffffffu, m, off));
            float e = __expf(a - m);
            float sum = e;
#pragma unroll
            for (int off = 16; off > 0; off >>= 1)
                sum += __shfl_xor_sync(0xffffffffu, sum, off);
            float al = e / sum;

            float4 acc = make_float4(0.0f, 0.0f, 0.0f, 0.0f);
#pragma unroll 8
            for (int k = 0; k < KNBR; k++) {
                int   nrow = __shfl_sync(0xffffffffu, idx, k);
                float ak   = __shfl_sync(0xffffffffu, al,  k);
                uint2 hv   = __ldg(ebase + (size_t)((unsigned)nrow) * (EMB / 4) + lane);
                __half2 h0 = *reinterpret_cast<__half2*>(&hv.x);
                __half2 h1 = *reinterpret_cast<__half2*>(&hv.y);
                float2 v0 = __half22float2(h0);
                float2 v1 = __half22float2(h1);
                acc.x = fmaf(ak, v0.x, acc.x);
                acc.y = fmaf(ak, v0.y, acc.y);
                acc.z = fmaf(ak, v1.x, acc.z);
                acc.w = fmaf(ak, v1.y, acc.w);
            }
            __half2 o0 = __float22half2_rn(make_float2(acc.x, acc.y));
            __half2 o1 = __float22half2_rn(make_float2(acc.z, acc.w));
            uint2 ow;
            ow.x = *reinterpret_cast<uint32_t*>(&o0);
            ow.y = *reinterpret_cast<uint32_t*>(&o1);
            *reinterpret_cast<uint2*>(&s_cat[row * CAT_LDH + 128 + lane * 4]) = ow;
        }

        asm volatile("cp.async.wait_group 0;" ::: "memory");
        __syncthreads();    // s_cat fully built

        // ---- Phase 2: MMA mainloop over K=256 ----
        float acc[32];
#pragma unroll
        for (int i = 0; i < 32; i++) acc[i] = 0.0f;

#pragma unroll
        for (int ks = 0; ks < 16; ks++) {
            const int k0 = ks * 16;
            uint32_t a[4];
            ldsm_x4(a[0], a[1], a[2], a[3], a_lane_addr + (uint32_t)(k0 * 2));
#pragma unroll
            for (int np = 0; np < 4; np++) {
                uint32_t b0, b1, b2, b3;
                ldsm_x4_t(b0, b1, b2, b3,
                          b_lane_addr + (uint32_t)((k0 * W_LDH + np * 16) * 2));
                mma16816(&acc[(np * 2 + 0) * 4], a, b0, b1);
                mma16816(&acc[(np * 2 + 1) * 4], a, b2, b3);
            }
        }

        // ---- Phase 3: epilogue (ef/agg fp16 from s_cat; bias fp32) ----
        const int r  = lane >> 2;
        const int cq = (lane & 3) * 2;
#pragma unroll
        for (int ti = 0; ti < 8; ti++) {
            int c = nb + ti * 8 + cq;
            float2 b2v = *reinterpret_cast<const float2*>(bias + c);
#pragma unroll
            for (int h = 0; h < 2; h++) {
                int frow = f0 + r + 8 * h;
                int f = fbase + frow;
                if (f >= F) continue;
                float x0 = acc[ti * 4 + 2 * h]     + b2v.x;
                float x1 = acc[ti * 4 + 2 * h + 1] + b2v.y;
                float g0 = 1.0f / (1.0f + __expf(-x0));
                float g1 = 1.0f / (1.0f + __expf(-x1));
                float2 ef = __half22float2(
                    *reinterpret_cast<const __half2*>(&s_cat[frow * CAT_LDH + c]));
                float2 ag = __half22float2(
                    *reinterpret_cast<const __half2*>(&s_cat[frow * CAT_LDH + 128 + c]));
                float2 o;
                o.x = g0 * ef.x + (1.0f - g0) * ag.x;
                o.y = g1 * ef.y + (1.0f - g1) * ag.y;
                *reinterpret_cast<float2*>(out + (size_t)f * EMB + c) = o;
            }
        }
    }
}

// ---------------------------------------------------------------------------
extern "C" void kernel_launch(void* const* d_in, const int* in_sizes, int n_in,
                              void* d_out, int out_size)
{
    const int*   adj   = (const int*)d_in[0];     // [F,32]
    const float* emb_i = (const float*)d_in[1];   // [N,128]
    const float* emb_f = (const float*)d_in[2];   // [F,128]
    const float* u     = (const float*)d_in[3];   // [128]
    const float* W     = (const float*)d_in[4];   // [128,256]
    const float* bias  = (const float*)d_in[5];   // [128]
    float*       out   = (float*)d_out;           // [F,128]

    const int F = in_sizes[0] / KNBR;
    const int N = in_sizes[1] / EMB;

    int nsm = 148;
    cudaDeviceGetAttribute(&nsm, cudaDevAttrMultiProcessorCount, 0);

    cudaFuncSetAttribute(fused_kernel,
                         cudaFuncAttributeMaxDynamicSharedMemorySize, SMEM_FUSED_B);

    reset_kernel<<<1, 1>>>();

    int nblk_p = (N + 7) / 8;                       // warp per node
    int nblk_c = ((size_t)F * EMB / 4 + 255) / 256; // float4 per thread
    pre_kernel<<<nblk_p + nblk_c, 256>>>(emb_i, emb_f, u, N, F, nblk_p);

    int ntiles = (F + TM - 1) / TM;
    int nblk = 2 * nsm;
    if (nblk > ntiles) nblk = ntiles;
    fused_kernel<<<nblk, 256, SMEM_FUSED_B>>>(adj, W, bias, out, F);
}

// round 9
// speedup vs baseline: 1.3509x; 1.3509x over previous
#include <cuda_runtime.h>
#include <cuda_fp16.h>
#include <cstdint>

// Problem constants: F=50000, K=32, E=128, N_NODE=100000
#define KNBR 32
#define EMB  128
#define MAXF 50000
#define MAXN 100000

// Scratch (no cudaMalloc allowed)
__device__ float g_p[MAXN];                                // 0.4 MB
__device__ alignas(16) __half g_emb_h[MAXN * EMB];         // 25.6 MB
__device__ alignas(16) __half g_aggh [MAXF * EMB];         // 12.8 MB

// ---------------------------------------------------------------------------
// PTX helpers
// ---------------------------------------------------------------------------
__device__ __forceinline__ void ldsm_x4(uint32_t& r0, uint32_t& r1,
                                        uint32_t& r2, uint32_t& r3, uint32_t a)
{
    asm volatile("ldmatrix.sync.aligned.m8n8.x4.shared.b16 {%0,%1,%2,%3}, [%4];"
                 : "=r"(r0), "=r"(r1), "=r"(r2), "=r"(r3) : "r"(a));
}
__device__ __forceinline__ void ldsm_x4_t(uint32_t& r0, uint32_t& r1,
                                          uint32_t& r2, uint32_t& r3, uint32_t a)
{
    asm volatile("ldmatrix.sync.aligned.m8n8.x4.trans.shared.b16 {%0,%1,%2,%3}, [%4];"
                 : "=r"(r0), "=r"(r1), "=r"(r2), "=r"(r3) : "r"(a));
}
__device__ __forceinline__ void mma16816(float* d, const uint32_t* a,
                                         uint32_t b0, uint32_t b1)
{
    asm volatile(
        "mma.sync.aligned.m16n8k16.row.col.f32.f16.f16.f32 "
        "{%0,%1,%2,%3}, {%4,%5,%6,%7}, {%8,%9}, {%0,%1,%2,%3};"
        : "+f"(d[0]), "+f"(d[1]), "+f"(d[2]), "+f"(d[3])
        : "r"(a[0]), "r"(a[1]), "r"(a[2]), "r"(a[3]), "r"(b0), "r"(b1));
}
__device__ __forceinline__ void cp_async16(uint32_t saddr, const void* gaddr)
{
    asm volatile("cp.async.cg.shared.global [%0], [%1], 16;"
                 :: "r"(saddr), "l"(gaddr));
}

// ---------------------------------------------------------------------------
// Kernel PRE: p[n] = dot(emb_i[n], u) + fp16 copy of emb_i. Warp per node.
// ---------------------------------------------------------------------------
__global__ __launch_bounds__(256) void pre_kernel(
    const float* __restrict__ emb_i, const float* __restrict__ u, int N)
{
    int gw   = (blockIdx.x * 256 + threadIdx.x) >> 5;
    int lane = threadIdx.x & 31;
    if (gw >= N) return;
    float4 v  = *reinterpret_cast<const float4*>(emb_i + (size_t)gw * EMB + lane * 4);
    float4 uu = *reinterpret_cast<const float4*>(u + lane * 4);

    __half2 h0 = __float22half2_rn(make_float2(v.x, v.y));
    __half2 h1 = __float22half2_rn(make_float2(v.z, v.w));
    uint2 hw;
    hw.x = *reinterpret_cast<uint32_t*>(&h0);
    hw.y = *reinterpret_cast<uint32_t*>(&h1);
    *reinterpret_cast<uint2*>(&g_emb_h[(size_t)gw * EMB + lane * 4]) = hw;

    float s = v.x * uu.x + v.y * uu.y + v.z * uu.z + v.w * uu.w;
#pragma unroll
    for (int off = 16; off > 0; off >>= 1)
        s += __shfl_xor_sync(0xffffffffu, s, off);
    if (lane == 0) g_p[gw] = s;
}

// ---------------------------------------------------------------------------
// Kernel B: fused softmax + aggregate, warp per feature.
// aggh[f,e] = fp16( sum_k softmax_k(p[adj[f,k]]+mask) * emb_h[adj[f,k], e] )
// Lane k holds (idx_k, alpha_k); gather loop broadcasts via shfl.
// 8B loads per lane (256B/warp per neighbor), unroll 16 for MLP.
// Writes ONLY fp16 g_aggh (12.8 MB).
// ---------------------------------------------------------------------------
__global__ __launch_bounds__(256) void agg_kernel(
    const int* __restrict__ adj, int F)
{
    const int f    = blockIdx.x * 8 + (threadIdx.x >> 5);
    const int lane = threadIdx.x & 31;
    if (f >= F) return;

    int   idx = adj[(size_t)f * KNBR + lane];
    float a = g_p[idx] + (idx != 0 ? 0.0f : -10000.0f);
    float m = a;
#pragma unroll
    for (int off = 16; off > 0; off >>= 1)
        m = fmaxf(m, __shfl_xor_sync(0xffffffffu, m, off));
    float e = __expf(a - m);
    float sum = e;
#pragma unroll
    for (int off = 16; off > 0; off >>= 1)
        sum += __shfl_xor_sync(0xffffffffu, sum, off);
    float al = e / sum;

    const uint2* base = reinterpret_cast<const uint2*>(g_emb_h);
    float4 acc = make_float4(0.0f, 0.0f, 0.0f, 0.0f);
#pragma unroll 16
    for (int k = 0; k < KNBR; k++) {
        int   row = __shfl_sync(0xffffffffu, idx, k);
        float ak  = __shfl_sync(0xffffffffu, al,  k);
        uint2 hv  = __ldg(base + (size_t)((unsigned)row) * (EMB / 4) + lane);
        __half2 h0 = *reinterpret_cast<__half2*>(&hv.x);
        __half2 h1 = *reinterpret_cast<__half2*>(&hv.y);
        float2 v0 = __half22float2(h0);
        float2 v1 = __half22float2(h1);
        acc.x = fmaf(ak, v0.x, acc.x);
        acc.y = fmaf(ak, v0.y, acc.y);
        acc.z = fmaf(ak, v1.x, acc.z);
        acc.w = fmaf(ak, v1.y, acc.w);
    }

    __half2 o0 = __float22half2_rn(make_float2(acc.x, acc.y));
    __half2 o1 = __float22half2_rn(make_float2(acc.z, acc.w));
    uint2 ow;
    ow.x = *reinterpret_cast<uint32_t*>(&o0);
    ow.y = *reinterpret_cast<uint32_t*>(&o1);
    *reinterpret_cast<uint2*>(&g_aggh[(size_t)f * EMB + lane * 4]) = ow;
}

// ---------------------------------------------------------------------------
// Kernel C: tensor-core gate+fuse, persistent, 2 CTAs/SM, static striding.
// Per 64-f tile: cp.async agg fp16 -> s_cat[:,128:256] (issued first),
// emb_f fp32 -> convert -> s_cat[:,0:128] (overlaps the cp.async flight),
// HMMA K=256, epilogue reads ef/agg fp16 from s_cat (no global reads but
// bias) and writes out fp32.
// 256 thr = 8 warps (4f x 2e); warp tile 16f x 64e.
// ---------------------------------------------------------------------------
#define TM 64
#define W_LDH   136                      // halves per k-row (128 + 8 pad)
#define CAT_LDH 264                      // halves per f-row (256 + 8 pad)
#define S_W_HALFS    (256 * W_LDH)       // 69632 B
#define S_CAT_HALFS  (TM * CAT_LDH)      // 33792 B
#define SMEM_GATE_B  ((S_W_HALFS + S_CAT_HALFS) * 2)     // 103424 B

__global__ __launch_bounds__(256, 2) void gate_fuse_kernel(
    const float* __restrict__ emb_f,  // [F, 128] fp32
    const float* __restrict__ W,      // [128, 256]
    const float* __restrict__ bias,   // [128]
    float* __restrict__ out,          // [F, 128]
    int F)
{
    extern __shared__ __half hsmem[];
    __half* s_w   = hsmem;                 // [k=0..255][n=0..127] (+pad)
    __half* s_cat = hsmem + S_W_HALFS;     // [f=0..63][k=0..255] (+pad)

    const int t    = threadIdx.x;
    const int lane = t & 31;
    const int wid  = t >> 5;
    const int f0   = (wid >> 1) * 16;
    const int nb   = (wid & 1) * 64;
    const int ntiles = (F + TM - 1) / TM;

    // ---- W -> fp16 smem [k][n] transposed, once per block ----
#pragma unroll
    for (int r = 0; r < 32; r++) {
        int id = t + 256 * r;             // 8192 float4 = 128e x 64jq
        int e  = id >> 6;
        int jq = id & 63;
        float4 v = *reinterpret_cast<const float4*>(W + e * 256 + jq * 4);
        s_w[(jq * 4 + 0) * W_LDH + e] = __float2half_rn(v.x);
        s_w[(jq * 4 + 1) * W_LDH + e] = __float2half_rn(v.y);
        s_w[(jq * 4 + 2) * W_LDH + e] = __float2half_rn(v.z);
        s_w[(jq * 4 + 3) * W_LDH + e] = __float2half_rn(v.w);
    }

    const uint32_t s_cat_u = (uint32_t)__cvta_generic_to_shared(s_cat);
    const uint32_t s_w_u   = (uint32_t)__cvta_generic_to_shared(s_w);

    const uint32_t a_lane_addr = s_cat_u +
        (uint32_t)(((f0 + (lane & 15)) * CAT_LDH + (lane >> 4) * 8) * 2);
    const uint32_t b_lane_addr = s_w_u +
        (uint32_t)(((((lane >> 3) & 1) * 8 + (lane & 7)) * W_LDH
                    + nb + (lane >> 4) * 8) * 2);

#pragma unroll 1
    for (int tile = blockIdx.x; tile < ntiles; tile += gridDim.x) {
        const int fbase = tile * TM;
        __syncthreads();    // prior epilogue done with s_cat (iter 0: W done)

        // ---- agg fp16 -> s_cat[:,128:256] via cp.async (issued first) ----
#pragma unroll
        for (int r = 0; r < 4; r++) {
            int id  = t + 256 * r;           // 1024 chunks of 16B
            int row = id >> 4;               // 0..63
            int c   = id & 15;               // chunk 0..15
            int gf  = fbase + row; if (gf >= F) gf = F - 1;
            cp_async16(s_cat_u + (uint32_t)((row * CAT_LDH + 128 + c * 8) * 2),
                       g_aggh + (size_t)gf * EMB + c * 8);
        }
        asm volatile("cp.async.commit_group;");

        // ---- emb_f fp32 -> fp16 -> s_cat[:,0:128] (overlaps cp.async) ----
#pragma unroll
        for (int r = 0; r < 8; r++) {
            int id  = t + 256 * r;           // 2048 float4 = 64 rows x 32
            int row = id >> 5;               // 0..63
            int q   = id & 31;               // float4 col
            int gf  = fbase + row; if (gf >= F) gf = F - 1;
            float4 v = *reinterpret_cast<const float4*>(
                emb_f + (size_t)gf * EMB + q * 4);
            __half2 h0 = __float22half2_rn(make_float2(v.x, v.y));
            __half2 h1 = __float22half2_rn(make_float2(v.z, v.w));
            uint2 hw;
            hw.x = *reinterpret_cast<uint32_t*>(&h0);
            hw.y = *reinterpret_cast<uint32_t*>(&h1);
            *reinterpret_cast<uint2*>(&s_cat[row * CAT_LDH + q * 4]) = hw;
        }

        asm volatile("cp.async.wait_group 0;" ::: "memory");
        __syncthreads();    // s_cat fully built

        // ---- MMA mainloop over K=256 ----
        float acc[32];
#pragma unroll
        for (int i = 0; i < 32; i++) acc[i] = 0.0f;

#pragma unroll
        for (int ks = 0; ks < 16; ks++) {
            const int k0 = ks * 16;
            uint32_t a[4];
            ldsm_x4(a[0], a[1], a[2], a[3], a_lane_addr + (uint32_t)(k0 * 2));
#pragma unroll
            for (int np = 0; np < 4; np++) {
                uint32_t b0, b1, b2, b3;
                ldsm_x4_t(b0, b1, b2, b3,
                          b_lane_addr + (uint32_t)((k0 * W_LDH + np * 16) * 2));
                mma16816(&acc[(np * 2 + 0) * 4], a, b0, b1);
                mma16816(&acc[(np * 2 + 1) * 4], a, b2, b3);
            }
        }

        // ---- Epilogue: ef/agg fp16 from s_cat (warp-local rows) ----
        const int r  = lane >> 2;
        const int cq = (lane & 3) * 2;
#pragma unroll
        for (int ti = 0; ti < 8; ti++) {
            int c = nb + ti * 8 + cq;
            float2 b2v = *reinterpret_cast<const float2*>(bias + c);
#pragma unroll
            for (int h = 0; h < 2; h++) {
                int frow = f0 + r + 8 * h;
                int f = fbase + frow;
                if (f >= F) continue;
                float x0 = acc[ti * 4 + 2 * h]     + b2v.x;
                float x1 = acc[ti * 4 + 2 * h + 1] + b2v.y;
                float g0 = 1.0f / (1.0f + __expf(-x0));
                float g1 = 1.0f / (1.0f + __expf(-x1));
                float2 ef = __half22float2(
                    *reinterpret_cast<const __half2*>(&s_cat[frow * CAT_LDH + c]));
                float2 ag = __half22float2(
                    *reinterpret_cast<const __half2*>(&s_cat[frow * CAT_LDH + 128 + c]));
                float2 o;
                o.x = g0 * ef.x + (1.0f - g0) * ag.x;
                o.y = g1 * ef.y + (1.0f - g1) * ag.y;
                *reinterpret_cast<float2*>(out + (size_t)f * EMB + c) = o;
            }
        }
    }
}

// ---------------------------------------------------------------------------
extern "C" void kernel_launch(void* const* d_in, const int* in_sizes, int n_in,
                              void* d_out, int out_size)
{
    const int*   adj   = (const int*)d_in[0];     // [F,32]
    const float* emb_i = (const float*)d_in[1];   // [N,128]
    const float* emb_f = (const float*)d_in[2];   // [F,128]
    const float* u     = (const float*)d_in[3];   // [128]
    const float* W     = (const float*)d_in[4];   // [128,256]
    const float* bias  = (const float*)d_in[5];   // [128]
    float*       out   = (float*)d_out;           // [F,128]

    const int F = in_sizes[0] / KNBR;
    const int N = in_sizes[1] / EMB;

    int nsm = 148;
    cudaDeviceGetAttribute(&nsm, cudaDevAttrMultiProcessorCount, 0);

    cudaFuncSetAttribute(gate_fuse_kernel,
                         cudaFuncAttributeMaxDynamicSharedMemorySize, SMEM_GATE_B);

    pre_kernel<<<(N * 32 + 255) / 256, 256>>>(emb_i, u, N);
    agg_kernel<<<(F + 7) / 8, 256>>>(adj, F);

    int ntiles = (F + TM - 1) / TM;
    int nblk = 2 * nsm;
    if (nblk > ntiles) nblk = ntiles;
    gate_fuse_kernel<<<nblk, 256, SMEM_GATE_B>>>(emb_f, W, bias, out, F);
}

// round 10
// speedup vs baseline: 1.5521x; 1.1489x over previous
#include <cuda_runtime.h>
#include <cuda_fp16.h>
#include <cstdint>

// Problem constants: F=50000, K=32, E=128, N_NODE=100000
#define KNBR 32
#define EMB  128
#define MAXF 50000
#define MAXN 100000

// Scratch (no cudaMalloc allowed)
__device__ float g_p[MAXN];                                // 0.4 MB
__device__ alignas(16) __half g_emb_h [MAXN * EMB];        // 25.6 MB
__device__ alignas(16) __half g_embf_h[MAXF * EMB];        // 12.8 MB
__device__ alignas(16) __half g_aggh  [MAXF * EMB];        // 12.8 MB

// ---------------------------------------------------------------------------
// PTX helpers
// ---------------------------------------------------------------------------
__device__ __forceinline__ void ldsm_x4(uint32_t& r0, uint32_t& r1,
                                        uint32_t& r2, uint32_t& r3, uint32_t a)
{
    asm volatile("ldmatrix.sync.aligned.m8n8.x4.shared.b16 {%0,%1,%2,%3}, [%4];"
                 : "=r"(r0), "=r"(r1), "=r"(r2), "=r"(r3) : "r"(a));
}
__device__ __forceinline__ void mma16816(float* d, const uint32_t* a,
                                         uint32_t b0, uint32_t b1)
{
    asm volatile(
        "mma.sync.aligned.m16n8k16.row.col.f32.f16.f16.f32 "
        "{%0,%1,%2,%3}, {%4,%5,%6,%7}, {%8,%9}, {%0,%1,%2,%3};"
        : "+f"(d[0]), "+f"(d[1]), "+f"(d[2]), "+f"(d[3])
        : "r"(a[0]), "r"(a[1]), "r"(a[2]), "r"(a[3]), "r"(b0), "r"(b1));
}
__device__ __forceinline__ void cp_async16(uint32_t saddr, const void* gaddr)
{
    asm volatile("cp.async.cg.shared.global [%0], [%1], 16;"
                 :: "r"(saddr), "l"(gaddr));
}

// ---------------------------------------------------------------------------
// Kernel PRE: blocks [0, nblk_p): p[n] = dot(emb_i[n], u) + fp16 copy of emb_i
//             blocks [nblk_p, ..): fp16 copy of emb_f
// ---------------------------------------------------------------------------
__global__ __launch_bounds__(256) void pre_kernel(
    const float* __restrict__ emb_i, const float* __restrict__ emb_f,
    const float* __restrict__ u, int N, int F, int nblk_p)
{
    if (blockIdx.x < (unsigned)nblk_p) {
        int gw   = (blockIdx.x * 256 + threadIdx.x) >> 5;
        int lane = threadIdx.x & 31;
        if (gw >= N) return;
        float4 v  = *reinterpret_cast<const float4*>(emb_i + (size_t)gw * EMB + lane * 4);
        float4 uu = *reinterpret_cast<const float4*>(u + lane * 4);

        __half2 h0 = __float22half2_rn(make_float2(v.x, v.y));
        __half2 h1 = __float22half2_rn(make_float2(v.z, v.w));
        uint2 hw;
        hw.x = *reinterpret_cast<uint32_t*>(&h0);
        hw.y = *reinterpret_cast<uint32_t*>(&h1);
        *reinterpret_cast<uint2*>(&g_emb_h[(size_t)gw * EMB + lane * 4]) = hw;

        float s = v.x * uu.x + v.y * uu.y + v.z * uu.z + v.w * uu.w;
#pragma unroll
        for (int off = 16; off > 0; off >>= 1)
            s += __shfl_xor_sync(0xffffffffu, s, off);
        if (lane == 0) g_p[gw] = s;
    } else {
        int id = (blockIdx.x - nblk_p) * 256 + threadIdx.x;   // float4 index
        size_t base = (size_t)id * 4;
        if (base >= (size_t)F * EMB) return;
        float4 v = *reinterpret_cast<const float4*>(emb_f + base);
        __half2 h0 = __float22half2_rn(make_float2(v.x, v.y));
        __half2 h1 = __float22half2_rn(make_float2(v.z, v.w));
        uint2 hw;
        hw.x = *reinterpret_cast<uint32_t*>(&h0);
        hw.y = *reinterpret_cast<uint32_t*>(&h1);
        *reinterpret_cast<uint2*>(&g_embf_h[base]) = hw;
    }
}

// ---------------------------------------------------------------------------
// Kernel B: fused softmax + aggregate, warp per feature.
// aggh[f,e] = fp16( sum_k softmax_k(p[adj[f,k]]+mask) * emb_h[adj[f,k], e] )
// ---------------------------------------------------------------------------
__global__ __launch_bounds__(256) void agg_kernel(
    const int* __restrict__ adj, int F)
{
    const int f    = blockIdx.x * 8 + (threadIdx.x >> 5);
    const int lane = threadIdx.x & 31;
    if (f >= F) return;

    int   idx = adj[(size_t)f * KNBR + lane];
    float a = g_p[idx] + (idx != 0 ? 0.0f : -10000.0f);
    float m = a;
#pragma unroll
    for (int off = 16; off > 0; off >>= 1)
        m = fmaxf(m, __shfl_xor_sync(0xffffffffu, m, off));
    float e = __expf(a - m);
    float sum = e;
#pragma unroll
    for (int off = 16; off > 0; off >>= 1)
        sum += __shfl_xor_sync(0xffffffffu, sum, off);
    float al = e / sum;

    const uint2* base = reinterpret_cast<const uint2*>(g_emb_h);
    float4 acc = make_float4(0.0f, 0.0f, 0.0f, 0.0f);
#pragma unroll 16
    for (int k = 0; k < KNBR; k++) {
        int   row = __shfl_sync(0xffffffffu, idx, k);
        float ak  = __shfl_sync(0xffffffffu, al,  k);
        uint2 hv  = __ldg(base + (size_t)((unsigned)row) * (EMB / 4) + lane);
        __half2 h0 = *reinterpret_cast<__half2*>(&hv.x);
        __half2 h1 = *reinterpret_cast<__half2*>(&hv.y);
        float2 v0 = __half22float2(h0);
        float2 v1 = __half22float2(h1);
        acc.x = fmaf(ak, v0.x, acc.x);
        acc.y = fmaf(ak, v0.y, acc.y);
        acc.z = fmaf(ak, v1.x, acc.z);
        acc.w = fmaf(ak, v1.y, acc.w);
    }

    __half2 o0 = __float22half2_rn(make_float2(acc.x, acc.y));
    __half2 o1 = __float22half2_rn(make_float2(acc.z, acc.w));
    uint2 ow;
    ow.x = *reinterpret_cast<uint32_t*>(&o0);
    ow.y = *reinterpret_cast<uint32_t*>(&o1);
    *reinterpret_cast<uint2*>(&g_aggh[(size_t)f * EMB + lane * 4]) = ow;
}

// ---------------------------------------------------------------------------
// Kernel C: tensor-core gate+fuse, persistent, 2 CTAs/SM.
// s_w stored [n][k] (direct vectorized copy of W, NO transpose); B fragments
// via NON-trans ldmatrix (col-major B = [n][k] rows, k contiguous).
// Full cat tile (emb_f fp16 | agg fp16) streamed via cp.async.
// Epilogue reads ef/agg fp16 from s_cat; writes out fp32.
// 256 thr = 8 warps (4f x 2e); warp tile 16f x 64e; K=256 in 16 steps.
// ---------------------------------------------------------------------------
#define TM 64
#define WK_LD   264                      // halves per n-row (256 + 8 pad)
#define CAT_LDH 264                      // halves per f-row (256 + 8 pad)
#define S_W_HALFS    (128 * WK_LD)       // 33792 halves = 67584 B
#define S_CAT_HALFS  (TM * CAT_LDH)      // 16896 halves = 33792 B
#define SMEM_GATE_B  ((S_W_HALFS + S_CAT_HALFS) * 2)     // 101376 B

__global__ __launch_bounds__(256, 2) void gate_fuse_kernel(
    const float* __restrict__ W,      // [128, 256] row-major (n=e, k=j)
    const float* __restrict__ bias,   // [128]
    float* __restrict__ out,          // [F, 128]
    int F)
{
    extern __shared__ __half hsmem[];
    __half* s_w   = hsmem;                 // [n=0..127][k=0..255] (+pad)
    __half* s_cat = hsmem + S_W_HALFS;     // [f=0..63][k=0..255] (+pad)

    const int t    = threadIdx.x;
    const int lane = t & 31;
    const int wid  = t >> 5;
    const int f0   = (wid >> 1) * 16;
    const int nb   = (wid & 1) * 64;
    const int ntiles = (F + TM - 1) / TM;

    const uint32_t s_cat_u = (uint32_t)__cvta_generic_to_shared(s_cat);
    const uint32_t s_w_u   = (uint32_t)__cvta_generic_to_shared(s_w);

    // ---- W -> fp16 smem [n][k], direct copy, vectorized (once per block) ----
#pragma unroll
    for (int r = 0; r < 32; r++) {
        int id = t + 256 * r;             // 8192 float4 = 128n x 64 k-quads
        int n  = id >> 6;                 // 0..127
        int kq = id & 63;                 // k = kq*4..kq*4+3
        float4 v = *reinterpret_cast<const float4*>(W + n * 256 + kq * 4);
        __half2 h0 = __float22half2_rn(make_float2(v.x, v.y));
        __half2 h1 = __float22half2_rn(make_float2(v.z, v.w));
        uint2 hw;
        hw.x = *reinterpret_cast<uint32_t*>(&h0);
        hw.y = *reinterpret_cast<uint32_t*>(&h1);
        *reinterpret_cast<uint2*>(&s_w[n * WK_LD + kq * 4]) = hw;
    }

    // ldmatrix lane addresses.
    // A (row-major [f][k]): lanes 0-15 rows f0..f0+15 kw0; 16-31 same rows kw8.
    const uint32_t a_lane_addr = s_cat_u +
        (uint32_t)(((f0 + (lane & 15)) * CAT_LDH + (lane >> 4) * 8) * 2);
    // B (col-major = [n][k] rows): tiles g0=(n0-7,k0-7) g1=(n0-7,k8-15)
    // g2=(n8-15,k0-7) g3=(n8-15,k8-15); lane L in group g supplies row ptr.
    const uint32_t b_lane_addr = s_w_u +
        (uint32_t)((((nb + (lane >> 4) * 8 + (lane & 7)) * WK_LD)
                    + ((lane >> 3) & 1) * 8) * 2);

#pragma unroll 1
    for (int tile = blockIdx.x; tile < ntiles; tile += gridDim.x) {
        const int fbase = tile * TM;
        __syncthreads();    // prior epilogue done with s_cat (iter 0: nothing)

        // ---- full cat tile via cp.async: [emb_f fp16 | agg fp16] ----
#pragma unroll
        for (int r = 0; r < 8; r++) {
            int id  = t + 256 * r;           // 2048 chunks of 16B
            int row = id >> 5;               // 0..63
            int c   = id & 31;               // chunk 0..31
            int gf  = fbase + row; if (gf >= F) gf = F - 1;
            const __half* src = (c < 16)
                ? (g_embf_h + (size_t)gf * EMB + c * 8)
                : (g_aggh   + (size_t)gf * EMB + (c - 16) * 8);
            cp_async16(s_cat_u + (uint32_t)((row * CAT_LDH + c * 8) * 2), src);
        }
        asm volatile("cp.async.commit_group;");
        asm volatile("cp.async.wait_group 0;" ::: "memory");
        __syncthreads();    // s_cat fully built (W done too, all iters)

        // ---- MMA mainloop over K=256 ----
        float acc[32];
#pragma unroll
        for (int i = 0; i < 32; i++) acc[i] = 0.0f;

#pragma unroll
        for (int ks = 0; ks < 16; ks++) {
            const int k0 = ks * 16;
            uint32_t a[4];
            ldsm_x4(a[0], a[1], a[2], a[3], a_lane_addr + (uint32_t)(k0 * 2));
#pragma unroll
            for (int np = 0; np < 4; np++) {
                uint32_t b0, b1, b2, b3;
                ldsm_x4(b0, b1, b2, b3,
                        b_lane_addr + (uint32_t)((np * 16 * WK_LD + k0) * 2));
                mma16816(&acc[(np * 2 + 0) * 4], a, b0, b1);
                mma16816(&acc[(np * 2 + 1) * 4], a, b2, b3);
            }
        }

        // ---- Epilogue: ef/agg fp16 from s_cat ----
        const int r  = lane >> 2;
        const int cq = (lane & 3) * 2;
#pragma unroll
        for (int ti = 0; ti < 8; ti++) {
            int c = nb + ti * 8 + cq;
            float2 b2v = *reinterpret_cast<const float2*>(bias + c);
#pragma unroll
            for (int h = 0; h < 2; h++) {
                int frow = f0 + r + 8 * h;
                int f = fbase + frow;
                if (f >= F) continue;
                float x0 = acc[ti * 4 + 2 * h]     + b2v.x;
                float x1 = acc[ti * 4 + 2 * h + 1] + b2v.y;
                float g0 = 1.0f / (1.0f + __expf(-x0));
                float g1 = 1.0f / (1.0f + __expf(-x1));
                float2 ef = __half22float2(
                    *reinterpret_cast<const __half2*>(&s_cat[frow * CAT_LDH + c]));
                float2 ag = __half22float2(
                    *reinterpret_cast<const __half2*>(&s_cat[frow * CAT_LDH + 128 + c]));
                float2 o;
                o.x = g0 * ef.x + (1.0f - g0) * ag.x;
                o.y = g1 * ef.y + (1.0f - g1) * ag.y;
                *reinterpret_cast<float2*>(out + (size_t)f * EMB + c) = o;
            }
        }
    }
}

// ---------------------------------------------------------------------------
extern "C" void kernel_launch(void* const* d_in, const int* in_sizes, int n_in,
                              void* d_out, int out_size)
{
    const int*   adj   = (const int*)d_in[0];     // [F,32]
    const float* emb_i = (const float*)d_in[1];   // [N,128]
    const float* emb_f = (const float*)d_in[2];   // [F,128]
    const float* u     = (const float*)d_in[3];   // [128]
    const float* W     = (const float*)d_in[4];   // [128,256]
    const float* bias  = (const float*)d_in[5];   // [128]
    float*       out   = (float*)d_out;           // [F,128]

    const int F = in_sizes[0] / KNBR;
    const int N = in_sizes[1] / EMB;

    int nsm = 148;
    cudaDeviceGetAttribute(&nsm, cudaDevAttrMultiProcessorCount, 0);

    cudaFuncSetAttribute(gate_fuse_kernel,
                         cudaFuncAttributeMaxDynamicSharedMemorySize, SMEM_GATE_B);

    int nblk_p = (N + 7) / 8;                       // warp per node
    int nblk_c = ((size_t)F * EMB / 4 + 255) / 256; // float4 per thread
    pre_kernel<<<nblk_p + nblk_c, 256>>>(emb_i, emb_f, u, N, F, nblk_p);

    agg_kernel<<<(F + 7) / 8, 256>>>(adj, F);

    int ntiles = (F + TM - 1) / TM;
    int nblk = 2 * nsm;
    if (nblk > ntiles) nblk = ntiles;
    gate_fuse_kernel<<<nblk, 256, SMEM_GATE_B>>>(W, bias, out, F);
}

// round 11
// speedup vs baseline: 1.6312x; 1.0510x over previous
#include <cuda_runtime.h>
#include <cuda_fp16.h>
#include <cstdint>

// Problem constants: F=50000, K=32, E=128, N_NODE=100000
#define KNBR 32
#define EMB  128
#define MAXF 50000
#define MAXN 100000

// Scratch (no cudaMalloc allowed)
__device__ float g_p[MAXN];                                // 0.4 MB
__device__ alignas(16) __half g_emb_h [MAXN * EMB];        // 25.6 MB
__device__ alignas(16) __half g_embf_h[MAXF * EMB];        // 12.8 MB
__device__ alignas(16) __half g_aggh  [MAXF * EMB];        // 12.8 MB

// ---------------------------------------------------------------------------
// PTX helpers
// ---------------------------------------------------------------------------
__device__ __forceinline__ void ldsm_x4(uint32_t& r0, uint32_t& r1,
                                        uint32_t& r2, uint32_t& r3, uint32_t a)
{
    asm volatile("ldmatrix.sync.aligned.m8n8.x4.shared.b16 {%0,%1,%2,%3}, [%4];"
                 : "=r"(r0), "=r"(r1), "=r"(r2), "=r"(r3) : "r"(a));
}
__device__ __forceinline__ void mma16816(float* d, const uint32_t* a,
                                         uint32_t b0, uint32_t b1)
{
    asm volatile(
        "mma.sync.aligned.m16n8k16.row.col.f32.f16.f16.f32 "
        "{%0,%1,%2,%3}, {%4,%5,%6,%7}, {%8,%9}, {%0,%1,%2,%3};"
        : "+f"(d[0]), "+f"(d[1]), "+f"(d[2]), "+f"(d[3])
        : "r"(a[0]), "r"(a[1]), "r"(a[2]), "r"(a[3]), "r"(b0), "r"(b1));
}
__device__ __forceinline__ void cp_async16(uint32_t saddr, const void* gaddr)
{
    asm volatile("cp.async.cg.shared.global [%0], [%1], 16;"
                 :: "r"(saddr), "l"(gaddr));
}

// ---------------------------------------------------------------------------
// Kernel PRE: blocks [0, nblk_p): p[n] = dot(emb_i[n], u) + fp16 copy of emb_i
//             blocks [nblk_p, ..): fp16 copy of emb_f
// ---------------------------------------------------------------------------
__global__ __launch_bounds__(256) void pre_kernel(
    const float* __restrict__ emb_i, const float* __restrict__ emb_f,
    const float* __restrict__ u, int N, int F, int nblk_p)
{
    if (blockIdx.x < (unsigned)nblk_p) {
        int gw   = (blockIdx.x * 256 + threadIdx.x) >> 5;
        int lane = threadIdx.x & 31;
        if (gw >= N) return;
        float4 v  = *reinterpret_cast<const float4*>(emb_i + (size_t)gw * EMB + lane * 4);
        float4 uu = *reinterpret_cast<const float4*>(u + lane * 4);

        __half2 h0 = __float22half2_rn(make_float2(v.x, v.y));
        __half2 h1 = __float22half2_rn(make_float2(v.z, v.w));
        uint2 hw;
        hw.x = *reinterpret_cast<uint32_t*>(&h0);
        hw.y = *reinterpret_cast<uint32_t*>(&h1);
        *reinterpret_cast<uint2*>(&g_emb_h[(size_t)gw * EMB + lane * 4]) = hw;

        float s = v.x * uu.x + v.y * uu.y + v.z * uu.z + v.w * uu.w;
#pragma unroll
        for (int off = 16; off > 0; off >>= 1)
            s += __shfl_xor_sync(0xffffffffu, s, off);
        if (lane == 0) g_p[gw] = s;
    } else {
        int id = (blockIdx.x - nblk_p) * 256 + threadIdx.x;   // float4 index
        size_t base = (size_t)id * 4;
        if (base >= (size_t)F * EMB) return;
        float4 v = *reinterpret_cast<const float4*>(emb_f + base);
        __half2 h0 = __float22half2_rn(make_float2(v.x, v.y));
        __half2 h1 = __float22half2_rn(make_float2(v.z, v.w));
        uint2 hw;
        hw.x = *reinterpret_cast<uint32_t*>(&h0);
        hw.y = *reinterpret_cast<uint32_t*>(&h1);
        *reinterpret_cast<uint2*>(&g_embf_h[base]) = hw;
    }
}

// ---------------------------------------------------------------------------
// Kernel B: fused softmax + aggregate, warp per feature, 16B gather lanes.
// 2 neighbors per iteration: lanes 0-15 -> neighbor 2k (uint4 = 8 halves),
// lanes 16-31 -> neighbor 2k+1. Variable-src shfl broadcasts (idx, alpha).
// Final shfl_xor(16) combine; lanes 0-15 store 16B fp16 each.
// ---------------------------------------------------------------------------
__global__ __launch_bounds__(256) void agg_kernel(
    const int* __restrict__ adj, int F)
{
    const int f    = blockIdx.x * 8 + (threadIdx.x >> 5);
    const int lane = threadIdx.x & 31;
    if (f >= F) return;

    // lane k owns neighbor k's (idx, alpha)
    int   idx = adj[(size_t)f * KNBR + lane];
    float a = g_p[idx] + (idx != 0 ? 0.0f : -10000.0f);
    float m = a;
#pragma unroll
    for (int off = 16; off > 0; off >>= 1)
        m = fmaxf(m, __shfl_xor_sync(0xffffffffu, m, off));
    float e = __expf(a - m);
    float sum = e;
#pragma unroll
    for (int off = 16; off > 0; off >>= 1)
        sum += __shfl_xor_sync(0xffffffffu, sum, off);
    float al = e / sum;

    const int half = lane >> 4;        // 0: even neighbors, 1: odd
    const int li   = lane & 15;        // element group: e = li*8 .. li*8+7

    const uint4* base = reinterpret_cast<const uint4*>(g_emb_h);
    float acc[8];
#pragma unroll
    for (int j = 0; j < 8; j++) acc[j] = 0.0f;

#pragma unroll 8
    for (int ki = 0; ki < KNBR / 2; ki++) {
        int src  = 2 * ki + half;
        int row  = __shfl_sync(0xffffffffu, idx, src);
        float ak = __shfl_sync(0xffffffffu, al,  src);
        uint4 hv = __ldg(base + (size_t)((unsigned)row) * (EMB / 8) + li);
        float2 v0 = __half22float2(*reinterpret_cast<__half2*>(&hv.x));
        float2 v1 = __half22float2(*reinterpret_cast<__half2*>(&hv.y));
        float2 v2 = __half22float2(*reinterpret_cast<__half2*>(&hv.z));
        float2 v3 = __half22float2(*reinterpret_cast<__half2*>(&hv.w));
        acc[0] = fmaf(ak, v0.x, acc[0]);
        acc[1] = fmaf(ak, v0.y, acc[1]);
        acc[2] = fmaf(ak, v1.x, acc[2]);
        acc[3] = fmaf(ak, v1.y, acc[3]);
        acc[4] = fmaf(ak, v2.x, acc[4]);
        acc[5] = fmaf(ak, v2.y, acc[5]);
        acc[6] = fmaf(ak, v3.x, acc[6]);
        acc[7] = fmaf(ak, v3.y, acc[7]);
    }

    // fold odd-neighbor partials (lanes 16-31) into lanes 0-15
#pragma unroll
    for (int j = 0; j < 8; j++)
        acc[j] += __shfl_xor_sync(0xffffffffu, acc[j], 16);

    if (half == 0) {
        __half2 o0 = __float22half2_rn(make_float2(acc[0], acc[1]));
        __half2 o1 = __float22half2_rn(make_float2(acc[2], acc[3]));
        __half2 o2 = __float22half2_rn(make_float2(acc[4], acc[5]));
        __half2 o3 = __float22half2_rn(make_float2(acc[6], acc[7]));
        uint4 ow;
        ow.x = *reinterpret_cast<uint32_t*>(&o0);
        ow.y = *reinterpret_cast<uint32_t*>(&o1);
        ow.z = *reinterpret_cast<uint32_t*>(&o2);
        ow.w = *reinterpret_cast<uint32_t*>(&o3);
        *reinterpret_cast<uint4*>(&g_aggh[(size_t)f * EMB + li * 8]) = ow;
    }
}

// ---------------------------------------------------------------------------
// Kernel C: tensor-core gate+fuse, persistent, 2 CTAs/SM.
// s_w stored [n][k] (direct vectorized copy of W, NO transpose); B fragments
// via NON-trans ldmatrix. Full cat tile (emb_f fp16 | agg fp16) via cp.async.
// Epilogue reads ef/agg fp16 from s_cat; writes out fp32.
// 256 thr = 8 warps (4f x 2e); warp tile 16f x 64e; K=256 in 16 steps.
// ---------------------------------------------------------------------------
#define TM 64
#define WK_LD   264                      // halves per n-row (256 + 8 pad)
#define CAT_LDH 264                      // halves per f-row (256 + 8 pad)
#define S_W_HALFS    (128 * WK_LD)       // 67584 B
#define S_CAT_HALFS  (TM * CAT_LDH)      // 33792 B
#define SMEM_GATE_B  ((S_W_HALFS + S_CAT_HALFS) * 2)     // 101376 B

__global__ __launch_bounds__(256, 2) void gate_fuse_kernel(
    const float* __restrict__ W,      // [128, 256] row-major (n=e, k=j)
    const float* __restrict__ bias,   // [128]
    float* __restrict__ out,          // [F, 128]
    int F)
{
    extern __shared__ __half hsmem[];
    __half* s_w   = hsmem;                 // [n=0..127][k=0..255] (+pad)
    __half* s_cat = hsmem + S_W_HALFS;     // [f=0..63][k=0..255] (+pad)

    const int t    = threadIdx.x;
    const int lane = t & 31;
    const int wid  = t >> 5;
    const int f0   = (wid >> 1) * 16;
    const int nb   = (wid & 1) * 64;
    const int ntiles = (F + TM - 1) / TM;

    const uint32_t s_cat_u = (uint32_t)__cvta_generic_to_shared(s_cat);
    const uint32_t s_w_u   = (uint32_t)__cvta_generic_to_shared(s_w);

    // ---- W -> fp16 smem [n][k], direct vectorized copy (once per block) ----
#pragma unroll
    for (int r = 0; r < 32; r++) {
        int id = t + 256 * r;             // 8192 float4 = 128n x 64 k-quads
        int n  = id >> 6;
        int kq = id & 63;
        float4 v = *reinterpret_cast<const float4*>(W + n * 256 + kq * 4);
        __half2 h0 = __float22half2_rn(make_float2(v.x, v.y));
        __half2 h1 = __float22half2_rn(make_float2(v.z, v.w));
        uint2 hw;
        hw.x = *reinterpret_cast<uint32_t*>(&h0);
        hw.y = *reinterpret_cast<uint32_t*>(&h1);
        *reinterpret_cast<uint2*>(&s_w[n * WK_LD + kq * 4]) = hw;
    }

    const uint32_t a_lane_addr = s_cat_u +
        (uint32_t)(((f0 + (lane & 15)) * CAT_LDH + (lane >> 4) * 8) * 2);
    const uint32_t b_lane_addr = s_w_u +
        (uint32_t)((((nb + (lane >> 4) * 8 + (lane & 7)) * WK_LD)
                    + ((lane >> 3) & 1) * 8) * 2);

#pragma unroll 1
    for (int tile = blockIdx.x; tile < ntiles; tile += gridDim.x) {
        const int fbase = tile * TM;
        __syncthreads();    // prior epilogue done with s_cat (iter 0: nothing)

        // ---- full cat tile via cp.async: [emb_f fp16 | agg fp16] ----
#pragma unroll
        for (int r = 0; r < 8; r++) {
            int id  = t + 256 * r;           // 2048 chunks of 16B
            int row = id >> 5;               // 0..63
            int c   = id & 31;               // chunk 0..31
            int gf  = fbase + row; if (gf >= F) gf = F - 1;
            const __half* src = (c < 16)
                ? (g_embf_h + (size_t)gf * EMB + c * 8)
                : (g_aggh   + (size_t)gf * EMB + (c - 16) * 8);
            cp_async16(s_cat_u + (uint32_t)((row * CAT_LDH + c * 8) * 2), src);
        }
        asm volatile("cp.async.commit_group;");
        asm volatile("cp.async.wait_group 0;" ::: "memory");
        __syncthreads();    // s_cat fully built (W done too, all iters)

        // ---- MMA mainloop over K=256 ----
        float acc[32];
#pragma unroll
        for (int i = 0; i < 32; i++) acc[i] = 0.0f;

#pragma unroll
        for (int ks = 0; ks < 16; ks++) {
            const int k0 = ks * 16;
            uint32_t a[4];
            ldsm_x4(a[0], a[1], a[2], a[3], a_lane_addr + (uint32_t)(k0 * 2));
#pragma unroll
            for (int np = 0; np < 4; np++) {
                uint32_t b0, b1, b2, b3;
                ldsm_x4(b0, b1, b2, b3,
                        b_lane_addr + (uint32_t)((np * 16 * WK_LD + k0) * 2));
                mma16816(&acc[(np * 2 + 0) * 4], a, b0, b1);
                mma16816(&acc[(np * 2 + 1) * 4], a, b2, b3);
            }
        }

        // ---- Epilogue: ef/agg fp16 from s_cat ----
        const int r  = lane >> 2;
        const int cq = (lane & 3) * 2;
#pragma unroll
        for (int ti = 0; ti < 8; ti++) {
            int c = nb + ti * 8 + cq;
            float2 b2v = *reinterpret_cast<const float2*>(bias + c);
#pragma unroll
            for (int h = 0; h < 2; h++) {
                int frow = f0 + r + 8 * h;
                int f = fbase + frow;
                if (f >= F) continue;
                float x0 = acc[ti * 4 + 2 * h]     + b2v.x;
                float x1 = acc[ti * 4 + 2 * h + 1] + b2v.y;
                float g0 = 1.0f / (1.0f + __expf(-x0));
                float g1 = 1.0f / (1.0f + __expf(-x1));
                float2 ef = __half22float2(
                    *reinterpret_cast<const __half2*>(&s_cat[frow * CAT_LDH + c]));
                float2 ag = __half22float2(
                    *reinterpret_cast<const __half2*>(&s_cat[frow * CAT_LDH + 128 + c]));
                float2 o;
                o.x = g0 * ef.x + (1.0f - g0) * ag.x;
                o.y = g1 * ef.y + (1.0f - g1) * ag.y;
                *reinterpret_cast<float2*>(out + (size_t)f * EMB + c) = o;
            }
        }
    }
}

// ---------------------------------------------------------------------------
extern "C" void kernel_launch(void* const* d_in, const int* in_sizes, int n_in,
                              void* d_out, int out_size)
{
    const int*   adj   = (const int*)d_in[0];     // [F,32]
    const float* emb_i = (const float*)d_in[1];   // [N,128]
    const float* emb_f = (const float*)d_in[2];   // [F,128]
    const float* u     = (const float*)d_in[3];   // [128]
    const float* W     = (const float*)d_in[4];   // [128,256]
    const float* bias  = (const float*)d_in[5];   // [128]
    float*       out   = (float*)d_out;           // [F,128]

    const int F = in_sizes[0] / KNBR;
    const int N = in_sizes[1] / EMB;

    int nsm = 148;
    cudaDeviceGetAttribute(&nsm, cudaDevAttrMultiProcessorCount, 0);

    cudaFuncSetAttribute(gate_fuse_kernel,
                         cudaFuncAttributeMaxDynamicSharedMemorySize, SMEM_GATE_B);

    int nblk_p = (N + 7) / 8;                       // warp per node
    int nblk_c = ((size_t)F * EMB / 4 + 255) / 256; // float4 per thread
    pre_kernel<<<nblk_p + nblk_c, 256>>>(emb_i, emb_f, u, N, F, nblk_p);

    agg_kernel<<<(F + 7) / 8, 256>>>(adj, F);

    int ntiles = (F + TM - 1) / TM;
    int nblk = 2 * nsm;
    if (nblk > ntiles) nblk = ntiles;
    gate_fuse_kernel<<<nblk, 256, SMEM_GATE_B>>>(W, bias, out, F);
}

// round 12
// speedup vs baseline: 1.7131x; 1.0502x over previous
#include <cuda_runtime.h>
#include <cuda_fp16.h>
#include <cstdint>

// Problem constants: F=50000, K=32, E=128, N_NODE=100000
#define KNBR 32
#define EMB  128
#define MAXF 50000
#define MAXN 100000

// Scratch (no cudaMalloc allowed)
__device__ float g_p[MAXN];                                // 0.4 MB
__device__ alignas(16) __half g_emb_h [MAXN * EMB];        // 25.6 MB
__device__ alignas(16) __half g_embf_h[MAXF * EMB];        // 12.8 MB
__device__ alignas(16) __half g_aggh  [MAXF * EMB];        // 12.8 MB

// ---------------------------------------------------------------------------
// PTX helpers
// ---------------------------------------------------------------------------
__device__ __forceinline__ void ldsm_x4(uint32_t& r0, uint32_t& r1,
                                        uint32_t& r2, uint32_t& r3, uint32_t a)
{
    asm volatile("ldmatrix.sync.aligned.m8n8.x4.shared.b16 {%0,%1,%2,%3}, [%4];"
                 : "=r"(r0), "=r"(r1), "=r"(r2), "=r"(r3) : "r"(a));
}
__device__ __forceinline__ void mma16816(float* d, const uint32_t* a,
                                         uint32_t b0, uint32_t b1)
{
    asm volatile(
        "mma.sync.aligned.m16n8k16.row.col.f32.f16.f16.f32 "
        "{%0,%1,%2,%3}, {%4,%5,%6,%7}, {%8,%9}, {%0,%1,%2,%3};"
        : "+f"(d[0]), "+f"(d[1]), "+f"(d[2]), "+f"(d[3])
        : "r"(a[0]), "r"(a[1]), "r"(a[2]), "r"(a[3]), "r"(b0), "r"(b1));
}
__device__ __forceinline__ void cp_async16(uint32_t saddr, const void* gaddr)
{
    asm volatile("cp.async.cg.shared.global [%0], [%1], 16;"
                 :: "r"(saddr), "l"(gaddr));
}

// ---------------------------------------------------------------------------
// Kernel PRE: p[n] = dot(emb_i[n], u) + fp16 copy of emb_i.
// 2 nodes per warp (two independent LDG.128 chains -> 2x MLP).
// ---------------------------------------------------------------------------
__global__ __launch_bounds__(256) void pre_kernel(
    const float* __restrict__ emb_i, const float* __restrict__ u, int N)
{
    const int wid  = threadIdx.x >> 5;
    const int lane = threadIdx.x & 31;
    const int n0 = (blockIdx.x * 8 + wid) * 2;
    if (n0 >= N) return;
    const int n1 = n0 + 1;
    const bool has1 = (n1 < N);

    float4 uu = *reinterpret_cast<const float4*>(u + lane * 4);
    float4 v0 = *reinterpret_cast<const float4*>(emb_i + (size_t)n0 * EMB + lane * 4);
    float4 v1 = has1
        ? *reinterpret_cast<const float4*>(emb_i + (size_t)n1 * EMB + lane * 4)
        : make_float4(0.f, 0.f, 0.f, 0.f);

    // fp16 copies
    {
        __half2 a0 = __float22half2_rn(make_float2(v0.x, v0.y));
        __half2 a1 = __float22half2_rn(make_float2(v0.z, v0.w));
        uint2 hw;
        hw.x = *reinterpret_cast<uint32_t*>(&a0);
        hw.y = *reinterpret_cast<uint32_t*>(&a1);
        *reinterpret_cast<uint2*>(&g_emb_h[(size_t)n0 * EMB + lane * 4]) = hw;
    }
    if (has1) {
        __half2 a0 = __float22half2_rn(make_float2(v1.x, v1.y));
        __half2 a1 = __float22half2_rn(make_float2(v1.z, v1.w));
        uint2 hw;
        hw.x = *reinterpret_cast<uint32_t*>(&a0);
        hw.y = *reinterpret_cast<uint32_t*>(&a1);
        *reinterpret_cast<uint2*>(&g_emb_h[(size_t)n1 * EMB + lane * 4]) = hw;
    }

    float s0 = v0.x * uu.x + v0.y * uu.y + v0.z * uu.z + v0.w * uu.w;
    float s1 = v1.x * uu.x + v1.y * uu.y + v1.z * uu.z + v1.w * uu.w;
#pragma unroll
    for (int off = 16; off > 0; off >>= 1) {
        s0 += __shfl_xor_sync(0xffffffffu, s0, off);
        s1 += __shfl_xor_sync(0xffffffffu, s1, off);
    }
    if (lane == 0) {
        g_p[n0] = s0;
        if (has1) g_p[n1] = s1;
    }
}

// ---------------------------------------------------------------------------
// Kernel B: blocks [0, nblk_f): fused softmax + aggregate (warp per feature,
//           16B gather lanes, 2 neighbors/iter).
//           blocks [nblk_f, ..): emb_f fp32 -> fp16 conversion (DRAM-bound,
//           overlaps the L2-bound gather).
// ---------------------------------------------------------------------------
__global__ __launch_bounds__(256) void agg_kernel(
    const int* __restrict__ adj, const float* __restrict__ emb_f,
    int F, int nblk_f)
{
    if (blockIdx.x >= (unsigned)nblk_f) {
        // ---- emb_f fp16 conversion lane ----
        int id = (blockIdx.x - nblk_f) * 256 + threadIdx.x;   // float4 index
        size_t base = (size_t)id * 4;
        if (base >= (size_t)F * EMB) return;
        float4 v = *reinterpret_cast<const float4*>(emb_f + base);
        __half2 h0 = __float22half2_rn(make_float2(v.x, v.y));
        __half2 h1 = __float22half2_rn(make_float2(v.z, v.w));
        uint2 hw;
        hw.x = *reinterpret_cast<uint32_t*>(&h0);
        hw.y = *reinterpret_cast<uint32_t*>(&h1);
        *reinterpret_cast<uint2*>(&g_embf_h[base]) = hw;
        return;
    }

    const int f    = blockIdx.x * 8 + (threadIdx.x >> 5);
    const int lane = threadIdx.x & 31;
    if (f >= F) return;

    // lane k owns neighbor k's (idx, alpha)
    int   idx = adj[(size_t)f * KNBR + lane];
    float a = g_p[idx] + (idx != 0 ? 0.0f : -10000.0f);
    float m = a;
#pragma unroll
    for (int off = 16; off > 0; off >>= 1)
        m = fmaxf(m, __shfl_xor_sync(0xffffffffu, m, off));
    float e = __expf(a - m);
    float sum = e;
#pragma unroll
    for (int off = 16; off > 0; off >>= 1)
        sum += __shfl_xor_sync(0xffffffffu, sum, off);
    float al = e / sum;

    const int half = lane >> 4;        // 0: even neighbors, 1: odd
    const int li   = lane & 15;        // element group: e = li*8 .. li*8+7

    const uint4* base = reinterpret_cast<const uint4*>(g_emb_h);
    float acc[8];
#pragma unroll
    for (int j = 0; j < 8; j++) acc[j] = 0.0f;

#pragma unroll 8
    for (int ki = 0; ki < KNBR / 2; ki++) {
        int src  = 2 * ki + half;
        int row  = __shfl_sync(0xffffffffu, idx, src);
        float ak = __shfl_sync(0xffffffffu, al,  src);
        uint4 hv = __ldg(base + (size_t)((unsigned)row) * (EMB / 8) + li);
        float2 v0 = __half22float2(*reinterpret_cast<__half2*>(&hv.x));
        float2 v1 = __half22float2(*reinterpret_cast<__half2*>(&hv.y));
        float2 v2 = __half22float2(*reinterpret_cast<__half2*>(&hv.z));
        float2 v3 = __half22float2(*reinterpret_cast<__half2*>(&hv.w));
        acc[0] = fmaf(ak, v0.x, acc[0]);
        acc[1] = fmaf(ak, v0.y, acc[1]);
        acc[2] = fmaf(ak, v1.x, acc[2]);
        acc[3] = fmaf(ak, v1.y, acc[3]);
        acc[4] = fmaf(ak, v2.x, acc[4]);
        acc[5] = fmaf(ak, v2.y, acc[5]);
        acc[6] = fmaf(ak, v3.x, acc[6]);
        acc[7] = fmaf(ak, v3.y, acc[7]);
    }

    // fold odd-neighbor partials (lanes 16-31) into lanes 0-15
#pragma unroll
    for (int j = 0; j < 8; j++)
        acc[j] += __shfl_xor_sync(0xffffffffu, acc[j], 16);

    if (half == 0) {
        __half2 o0 = __float22half2_rn(make_float2(acc[0], acc[1]));
        __half2 o1 = __float22half2_rn(make_float2(acc[2], acc[3]));
        __half2 o2 = __float22half2_rn(make_float2(acc[4], acc[5]));
        __half2 o3 = __float22half2_rn(make_float2(acc[6], acc[7]));
        uint4 ow;
        ow.x = *reinterpret_cast<uint32_t*>(&o0);
        ow.y = *reinterpret_cast<uint32_t*>(&o1);
        ow.z = *reinterpret_cast<uint32_t*>(&o2);
        ow.w = *reinterpret_cast<uint32_t*>(&o3);
        *reinterpret_cast<uint4*>(&g_aggh[(size_t)f * EMB + li * 8]) = ow;
    }
}

// ---------------------------------------------------------------------------
// Kernel C: tensor-core gate+fuse, persistent, 2 CTAs/SM.
// s_w stored [n][k] (direct vectorized copy of W, NO transpose); B fragments
// via NON-trans ldmatrix. Full cat tile (emb_f fp16 | agg fp16) via cp.async.
// Epilogue reads ef/agg fp16 from s_cat; writes out fp32.
// 256 thr = 8 warps (4f x 2e); warp tile 16f x 64e; K=256 in 16 steps.
// ---------------------------------------------------------------------------
#define TM 64
#define WK_LD   264                      // halves per n-row (256 + 8 pad)
#define CAT_LDH 264                      // halves per f-row (256 + 8 pad)
#define S_W_HALFS    (128 * WK_LD)       // 67584 B
#define S_CAT_HALFS  (TM * CAT_LDH)      // 33792 B
#define SMEM_GATE_B  ((S_W_HALFS + S_CAT_HALFS) * 2)     // 101376 B

__global__ __launch_bounds__(256, 2) void gate_fuse_kernel(
    const float* __restrict__ W,      // [128, 256] row-major (n=e, k=j)
    const float* __restrict__ bias,   // [128]
    float* __restrict__ out,          // [F, 128]
    int F)
{
    extern __shared__ __half hsmem[];
    __half* s_w   = hsmem;                 // [n=0..127][k=0..255] (+pad)
    __half* s_cat = hsmem + S_W_HALFS;     // [f=0..63][k=0..255] (+pad)

    const int t    = threadIdx.x;
    const int lane = t & 31;
    const int wid  = t >> 5;
    const int f0   = (wid >> 1) * 16;
    const int nb   = (wid & 1) * 64;
    const int ntiles = (F + TM - 1) / TM;

    const uint32_t s_cat_u = (uint32_t)__cvta_generic_to_shared(s_cat);
    const uint32_t s_w_u   = (uint32_t)__cvta_generic_to_shared(s_w);

    // ---- W -> fp16 smem [n][k], direct vectorized copy (once per block) ----
#pragma unroll
    for (int r = 0; r < 32; r++) {
        int id = t + 256 * r;             // 8192 float4 = 128n x 64 k-quads
        int n  = id >> 6;
        int kq = id & 63;
        float4 v = *reinterpret_cast<const float4*>(W + n * 256 + kq * 4);
        __half2 h0 = __float22half2_rn(make_float2(v.x, v.y));
        __half2 h1 = __float22half2_rn(make_float2(v.z, v.w));
        uint2 hw;
        hw.x = *reinterpret_cast<uint32_t*>(&h0);
        hw.y = *reinterpret_cast<uint32_t*>(&h1);
        *reinterpret_cast<uint2*>(&s_w[n * WK_LD + kq * 4]) = hw;
    }

    const uint32_t a_lane_addr = s_cat_u +
        (uint32_t)(((f0 + (lane & 15)) * CAT_LDH + (lane >> 4) * 8) * 2);
    const uint32_t b_lane_addr = s_w_u +
        (uint32_t)((((nb + (lane >> 4) * 8 + (lane & 7)) * WK_LD)
                    + ((lane >> 3) & 1) * 8) * 2);

#pragma unroll 1
    for (int tile = blockIdx.x; tile < ntiles; tile += gridDim.x) {
        const int fbase = tile * TM;
        __syncthreads();    // prior epilogue done with s_cat (iter 0: nothing)

        // ---- full cat tile via cp.async: [emb_f fp16 | agg fp16] ----
#pragma unroll
        for (int r = 0; r < 8; r++) {
            int id  = t + 256 * r;           // 2048 chunks of 16B
            int row = id >> 5;               // 0..63
            int c   = id & 31;               // chunk 0..31
            int gf  = fbase + row; if (gf >= F) gf = F - 1;
            const __half* src = (c < 16)
                ? (g_embf_h + (size_t)gf * EMB + c * 8)
                : (g_aggh   + (size_t)gf * EMB + (c - 16) * 8);
            cp_async16(s_cat_u + (uint32_t)((row * CAT_LDH + c * 8) * 2), src);
        }
        asm volatile("cp.async.commit_group;");
        asm volatile("cp.async.wait_group 0;" ::: "memory");
        __syncthreads();    // s_cat fully built (W done too, all iters)

        // ---- MMA mainloop over K=256 ----
        float acc[32];
#pragma unroll
        for (int i = 0; i < 32; i++) acc[i] = 0.0f;

#pragma unroll
        for (int ks = 0; ks < 16; ks++) {
            const int k0 = ks * 16;
            uint32_t a[4];
            ldsm_x4(a[0], a[1], a[2], a[3], a_lane_addr + (uint32_t)(k0 * 2));
#pragma unroll
            for (int np = 0; np < 4; np++) {
                uint32_t b0, b1, b2, b3;
                ldsm_x4(b0, b1, b2, b3,
                        b_lane_addr + (uint32_t)((np * 16 * WK_LD + k0) * 2));
                mma16816(&acc[(np * 2 + 0) * 4], a, b0, b1);
                mma16816(&acc[(np * 2 + 1) * 4], a, b2, b3);
            }
        }

        // ---- Epilogue: ef/agg fp16 from s_cat ----
        const int r  = lane >> 2;
        const int cq = (lane & 3) * 2;
#pragma unroll
        for (int ti = 0; ti < 8; ti++) {
            int c = nb + ti * 8 + cq;
            float2 b2v = *reinterpret_cast<const float2*>(bias + c);
#pragma unroll
            for (int h = 0; h < 2; h++) {
                int frow = f0 + r + 8 * h;
                int f = fbase + frow;
                if (f >= F) continue;
                float x0 = acc[ti * 4 + 2 * h]     + b2v.x;
                float x1 = acc[ti * 4 + 2 * h + 1] + b2v.y;
                float g0 = 1.0f / (1.0f + __expf(-x0));
                float g1 = 1.0f / (1.0f + __expf(-x1));
                float2 ef = __half22float2(
                    *reinterpret_cast<const __half2*>(&s_cat[frow * CAT_LDH + c]));
                float2 ag = __half22float2(
                    *reinterpret_cast<const __half2*>(&s_cat[frow * CAT_LDH + 128 + c]));
                float2 o;
                o.x = g0 * ef.x + (1.0f - g0) * ag.x;
                o.y = g1 * ef.y + (1.0f - g1) * ag.y;
                *reinterpret_cast<float2*>(out + (size_t)f * EMB + c) = o;
            }
        }
    }
}

// ---------------------------------------------------------------------------
extern "C" void kernel_launch(void* const* d_in, const int* in_sizes, int n_in,
                              void* d_out, int out_size)
{
    const int*   adj   = (const int*)d_in[0];     // [F,32]
    const float* emb_i = (const float*)d_in[1];   // [N,128]
    const float* emb_f = (const float*)d_in[2];   // [F,128]
    const float* u     = (const float*)d_in[3];   // [128]
    const float* W     = (const float*)d_in[4];   // [128,256]
    const float* bias  = (const float*)d_in[5];   // [128]
    float*       out   = (float*)d_out;           // [F,128]

    const int F = in_sizes[0] / KNBR;
    const int N = in_sizes[1] / EMB;

    int nsm = 148;
    cudaDeviceGetAttribute(&nsm, cudaDevAttrMultiProcessorCount, 0);

    cudaFuncSetAttribute(gate_fuse_kernel,
                         cudaFuncAttributeMaxDynamicSharedMemorySize, SMEM_GATE_B);

    // pre: 16 nodes per block (2 per warp)
    int nblk_pre = (((N + 1) / 2) + 7) / 8;
    pre_kernel<<<nblk_pre, 256>>>(emb_i, u, N);

    // agg: gather blocks + embf-conversion blocks (independent, overlapped)
    int nblk_f = (F + 7) / 8;
    int nblk_c = (int)(((size_t)F * EMB / 4 + 255) / 256);
    agg_kernel<<<nblk_f + nblk_c, 256>>>(adj, emb_f, F, nblk_f);

    int ntiles = (F + TM - 1) / TM;
    int nblk = 2 * nsm;
    if (nblk > ntiles) nblk = ntiles;
    gate_fuse_kernel<<<nblk, 256, SMEM_GATE_B>>>(W, bias, out, F);
}